// round 3
// baseline (speedup 1.0000x reference)
#include <cuda_runtime.h>
#include <math.h>

// Problem constants (fixed by the reference)
#define BB   2
#define SS   2048
#define HH   1024
#define NHH  16
#define PHH  64
#define MM   (BB*SS)     // 4096 rows for all GEMMs
#define KK   1024        // GEMM reduction dim

// Scratch (allocation-free rule: __device__ globals)
__device__ float g_q[BB*NHH*SS*PHH];
__device__ float g_k[BB*NHH*SS*PHH];
__device__ float g_v[BB*NHH*SS*PHH];
__device__ float g_ctx[BB*SS*HH];

// ---------------------------------------------------------------------------
// GEMM: C = A @ W^T + bias.  A [M,K] row-major, W [N,K] row-major (NT gemm).
// 128x128 tile, BK=16, 256 threads, each thread computes a 2x2 grid of 4x4
// sub-tiles (8x8 results). SPLIT=true writes output in [B,NH,S,PH] layout.
// ---------------------------------------------------------------------------
template<bool SPLIT>
__global__ __launch_bounds__(256) void gemm_nt(const float* __restrict__ A,
                                               const float* __restrict__ W,
                                               const float* __restrict__ bias,
                                               float* __restrict__ C)
{
    __shared__ float As[16][132];
    __shared__ float Bs[16][132];

    const int tid = threadIdx.x;
    const int bm = blockIdx.y * 128;
    const int bn = blockIdx.x * 128;
    const int tx = tid & 15;   // 0..15
    const int ty = tid >> 4;   // 0..15

    float c[2][2][4][4];
#pragma unroll
    for (int ia = 0; ia < 2; ia++)
#pragma unroll
        for (int jb = 0; jb < 2; jb++)
#pragma unroll
            for (int i = 0; i < 4; i++)
#pragma unroll
                for (int j = 0; j < 4; j++) c[ia][jb][i][j] = 0.f;

    for (int k0 = 0; k0 < KK; k0 += 16) {
        // load 128x16 tiles of A and W, transposed into [k][m]/[k][n]
#pragma unroll
        for (int l = 0; l < 2; l++) {
            int idx = tid + l * 256;          // 0..511
            int row = idx >> 2;               // 0..127
            int qq  = idx & 3;                // which float4 within the 16-wide k
            float4 av = *(const float4*)&A[(size_t)(bm + row) * KK + k0 + qq * 4];
            As[qq*4+0][row] = av.x; As[qq*4+1][row] = av.y;
            As[qq*4+2][row] = av.z; As[qq*4+3][row] = av.w;
            float4 wv = *(const float4*)&W[(size_t)(bn + row) * KK + k0 + qq * 4];
            Bs[qq*4+0][row] = wv.x; Bs[qq*4+1][row] = wv.y;
            Bs[qq*4+2][row] = wv.z; Bs[qq*4+3][row] = wv.w;
        }
        __syncthreads();

#pragma unroll
        for (int k = 0; k < 16; k++) {
            float a0[4], a1[4], b0[4], b1[4];
            *(float4*)a0 = *(const float4*)&As[k][ty * 4];
            *(float4*)a1 = *(const float4*)&As[k][64 + ty * 4];
            *(float4*)b0 = *(const float4*)&Bs[k][tx * 4];
            *(float4*)b1 = *(const float4*)&Bs[k][64 + tx * 4];
#pragma unroll
            for (int i = 0; i < 4; i++)
#pragma unroll
                for (int j = 0; j < 4; j++) {
                    c[0][0][i][j] += a0[i] * b0[j];
                    c[0][1][i][j] += a0[i] * b1[j];
                    c[1][0][i][j] += a1[i] * b0[j];
                    c[1][1][i][j] += a1[i] * b1[j];
                }
        }
        __syncthreads();
    }

    // epilogue
#pragma unroll
    for (int ia = 0; ia < 2; ia++)
#pragma unroll
        for (int i = 0; i < 4; i++) {
            int mrow = bm + ia * 64 + ty * 4 + i;
            int b = mrow >> 11;        // / 2048
            int s = mrow & 2047;
#pragma unroll
            for (int jb = 0; jb < 2; jb++)
#pragma unroll
                for (int j = 0; j < 4; j++) {
                    int ncol = bn + jb * 64 + tx * 4 + j;
                    float val = c[ia][jb][i][j] + bias[ncol];
                    if (SPLIT) {
                        int h = ncol >> 6;
                        int d = ncol & 63;
                        g_dummy_noop: ;
                        C[(((size_t)(b * NHH + h)) * SS + s) * PHH + d] = val;
                    } else {
                        C[(size_t)mrow * HH + ncol] = val;
                    }
                }
        }
}

// ---------------------------------------------------------------------------
// Attention with online softmax + multiplicative mask.
// Grid: (S/64, NH, B). 256 threads. Each block owns 64 query rows of one head.
// Thread t handles q-row r = t/4; sub-group c4 = t%4 owns 16 k-cols (scores)
// and 16 output dims (PV phase).
// ---------------------------------------------------------------------------
#define ATTN_SMEM (4 * 64 * 68 * 4)

__global__ __launch_bounds__(256) void attn_kernel(const float* __restrict__ Q,
                                                   const float* __restrict__ K,
                                                   const float* __restrict__ V,
                                                   const float* __restrict__ mask,
                                                   float* __restrict__ ctx)
{
    extern __shared__ float sm[];
    float* Qs = sm;               // [64][68]  Qs[r][d]
    float* Kt = Qs + 64 * 68;     // [64][68]  Kt[d][kk]  (transposed)
    float* Vs = Kt + 64 * 68;     // [64][68]  Vs[kk][d]
    float* Ps = Vs + 64 * 68;     // [64][68]  Ps[r][kk]  (probabilities)

    const int t  = threadIdx.x;
    const int qt = blockIdx.x;
    const int h  = blockIdx.y;
    const int b  = blockIdx.z;
    const int r  = t >> 2;        // q row within tile
    const int c4 = t & 3;
    const int kk0 = c4 * 16;
    const int d0  = c4 * 16;
    const int q0  = qt * 64;

    const size_t headoff = ((size_t)(b * NHH + h)) * SS * PHH;
    const float* Qg = Q + headoff + (size_t)q0 * PHH;
    const float* Kg = K + headoff;
    const float* Vg = V + headoff;
    const float* Mg = mask + ((size_t)b * SS + q0) * SS;

    // load Q tile (64 x 64)
    for (int i = t; i < 64 * 16; i += 256) {
        int row = i >> 4, q = i & 15;
        float4 v = *(const float4*)&Qg[row * 64 + q * 4];
        float* dst = &Qs[row * 68 + q * 4];
        dst[0] = v.x; dst[1] = v.y; dst[2] = v.z; dst[3] = v.w;
    }

    float m = -3.0e38f, l = 0.f;
    float o[16];
#pragma unroll
    for (int i = 0; i < 16; i++) o[i] = 0.f;

    for (int kt = 0; kt < SS / 64; kt++) {
        __syncthreads();   // previous tile's Vs/Ps reads complete
        // load K (transposed) and V tiles
        for (int i = t; i < 1024; i += 256) {
            int row = i >> 4, q = i & 15;
            float4 kv = *(const float4*)&Kg[(size_t)(kt * 64 + row) * 64 + q * 4];
            Kt[(q * 4 + 0) * 68 + row] = kv.x;
            Kt[(q * 4 + 1) * 68 + row] = kv.y;
            Kt[(q * 4 + 2) * 68 + row] = kv.z;
            Kt[(q * 4 + 3) * 68 + row] = kv.w;
            float4 vv = *(const float4*)&Vg[(size_t)(kt * 64 + row) * 64 + q * 4];
            float* vd = &Vs[row * 68 + q * 4];
            vd[0] = vv.x; vd[1] = vv.y; vd[2] = vv.z; vd[3] = vv.w;
        }
        __syncthreads();

        // ---- scores: acc[j] = Q[r,:] . K[kk0+j,:] ----
        float acc[16];
#pragma unroll
        for (int j = 0; j < 16; j++) acc[j] = 0.f;
#pragma unroll 4
        for (int d = 0; d < 64; d++) {
            float qv = Qs[r * 68 + d];
            const float4* krow = (const float4*)&Kt[d * 68 + kk0];
            float4 k0v = krow[0], k1v = krow[1], k2v = krow[2], k3v = krow[3];
            acc[0]  += qv * k0v.x; acc[1]  += qv * k0v.y;
            acc[2]  += qv * k0v.z; acc[3]  += qv * k0v.w;
            acc[4]  += qv * k1v.x; acc[5]  += qv * k1v.y;
            acc[6]  += qv * k1v.z; acc[7]  += qv * k1v.w;
            acc[8]  += qv * k2v.x; acc[9]  += qv * k2v.y;
            acc[10] += qv * k2v.z; acc[11] += qv * k2v.w;
            acc[12] += qv * k3v.x; acc[13] += qv * k3v.y;
            acc[14] += qv * k3v.z; acc[15] += qv * k3v.w;
        }

        // scale + multiplicative mask
        const float4* mrow = (const float4*)&Mg[(size_t)r * SS + kt * 64 + kk0];
#pragma unroll
        for (int q = 0; q < 4; q++) {
            float4 mv = mrow[q];
            acc[q*4+0] = acc[q*4+0] * 0.125f * mv.x;
            acc[q*4+1] = acc[q*4+1] * 0.125f * mv.y;
            acc[q*4+2] = acc[q*4+2] * 0.125f * mv.z;
            acc[q*4+3] = acc[q*4+3] * 0.125f * mv.w;
        }

        // row max over the 64-wide tile (4 lanes per row)
        float tm = acc[0];
#pragma unroll
        for (int j = 1; j < 16; j++) tm = fmaxf(tm, acc[j]);
        tm = fmaxf(tm, __shfl_xor_sync(0xffffffffu, tm, 1));
        tm = fmaxf(tm, __shfl_xor_sync(0xffffffffu, tm, 2));

        float mnew = fmaxf(m, tm);
        float corr = __expf(m - mnew);
        float ts = 0.f;
#pragma unroll
        for (int j = 0; j < 16; j++) {
            float p = __expf(acc[j] - mnew);
            acc[j] = p;
            ts += p;
        }
        ts += __shfl_xor_sync(0xffffffffu, ts, 1);
        ts += __shfl_xor_sync(0xffffffffu, ts, 2);
        l = l * corr + ts;
        m = mnew;

        // publish probabilities
        float4* prow = (float4*)&Ps[r * 68 + kk0];
        prow[0] = make_float4(acc[0],  acc[1],  acc[2],  acc[3]);
        prow[1] = make_float4(acc[4],  acc[5],  acc[6],  acc[7]);
        prow[2] = make_float4(acc[8],  acc[9],  acc[10], acc[11]);
        prow[3] = make_float4(acc[12], acc[13], acc[14], acc[15]);
        __syncthreads();

        // ---- PV accumulation: o[d] = corr*o[d] + sum_kk P[r,kk]*V[kk,d] ----
#pragma unroll
        for (int i = 0; i < 16; i++) o[i] *= corr;
#pragma unroll 4
        for (int kk = 0; kk < 64; kk++) {
            float p = Ps[r * 68 + kk];
            const float4* vrow = (const float4*)&Vs[kk * 68 + d0];
            float4 v0 = vrow[0], v1 = vrow[1], v2 = vrow[2], v3 = vrow[3];
            o[0]  += p * v0.x; o[1]  += p * v0.y; o[2]  += p * v0.z; o[3]  += p * v0.w;
            o[4]  += p * v1.x; o[5]  += p * v1.y; o[6]  += p * v1.z; o[7]  += p * v1.w;
            o[8]  += p * v2.x; o[9]  += p * v2.y; o[10] += p * v2.z; o[11] += p * v2.w;
            o[12] += p * v3.x; o[13] += p * v3.y; o[14] += p * v3.z; o[15] += p * v3.w;
        }
    }

    // epilogue: ctx[b, q0+r, h*64 + d0 .. +15] = o / l
    float inv = 1.f / l;
    float* og = &ctx[((size_t)b * SS + q0 + r) * HH + h * PHH + d0];
#pragma unroll
    for (int q = 0; q < 4; q++) {
        float4 v = make_float4(o[q*4+0] * inv, o[q*4+1] * inv,
                               o[q*4+2] * inv, o[q*4+3] * inv);
        *(float4*)&og[q * 4] = v;
    }
}

// ---------------------------------------------------------------------------
// Launch
// ---------------------------------------------------------------------------
extern "C" void kernel_launch(void* const* d_in, const int* in_sizes, int n_in,
                              void* d_out, int out_size)
{
    const float* key   = (const float*)d_in[0];
    const float* value = (const float*)d_in[1];
    const float* query = (const float*)d_in[2];
    const float* mask  = (const float*)d_in[3];
    // d_in[4] = i (unused)
    const float* Wq = (const float*)d_in[5];
    const float* bq = (const float*)d_in[6];
    const float* Wk = (const float*)d_in[7];
    const float* bk = (const float*)d_in[8];
    const float* Wv = (const float*)d_in[9];
    const float* bv = (const float*)d_in[10];
    const float* Wo = (const float*)d_in[11];
    const float* bo = (const float*)d_in[12];
    float* out = (float*)d_out;

    float *qp, *kp, *vp, *cp;
    cudaGetSymbolAddress((void**)&qp, g_q);
    cudaGetSymbolAddress((void**)&kp, g_k);
    cudaGetSymbolAddress((void**)&vp, g_v);
    cudaGetSymbolAddress((void**)&cp, g_ctx);

    dim3 gg(HH / 128, MM / 128);   // (8, 32)

    gemm_nt<true><<<gg, 256>>>(query, Wq, bq, qp);
    gemm_nt<true><<<gg, 256>>>(key,   Wk, bk, kp);
    gemm_nt<true><<<gg, 256>>>(value, Wv, bv, vp);

    cudaFuncSetAttribute(attn_kernel,
                         cudaFuncAttributeMaxDynamicSharedMemorySize, ATTN_SMEM);
    attn_kernel<<<dim3(SS / 64, NHH, BB), 256, ATTN_SMEM>>>(qp, kp, vp, mask, cp);

    gemm_nt<false><<<gg, 256>>>(cp, Wo, bo, out);
}

// round 4
// speedup vs baseline: 2.5241x; 2.5241x over previous
#include <cuda_runtime.h>
#include <math.h>

// Problem constants (fixed by the reference)
#define BB   2
#define SS   2048
#define HH   1024
#define NHH  16
#define PHH  64
#define MM   (BB*SS)     // 4096 rows for all GEMMs
#define KK   1024        // GEMM reduction dim

// Scratch (allocation-free rule: __device__ globals)
__device__ float g_q[BB*NHH*SS*PHH];
__device__ float g_k[BB*NHH*SS*PHH];
__device__ float g_v[BB*NHH*SS*PHH];
__device__ float g_ctx[BB*SS*HH];

// ---------------------------------------------------------------------------
// GEMM: C = A @ W^T + bias.  A [M,K] row-major, W [N,K] row-major (NT gemm).
// 128x128 tile, BK=16, 256 threads, 8x8 results per thread (2x2 of 4x4).
// SPLIT=true writes output in [B,NH,S,PH] layout.
// ---------------------------------------------------------------------------
template<bool SPLIT>
__global__ __launch_bounds__(256) void gemm_nt(const float* __restrict__ A,
                                               const float* __restrict__ W,
                                               const float* __restrict__ bias,
                                               float* __restrict__ C)
{
    __shared__ float As[16][132];
    __shared__ float Bs[16][132];

    const int tid = threadIdx.x;
    const int bm = blockIdx.y * 128;
    const int bn = blockIdx.x * 128;
    const int tx = tid & 15;   // 0..15
    const int ty = tid >> 4;   // 0..15

    float c[2][2][4][4];
#pragma unroll
    for (int ia = 0; ia < 2; ia++)
#pragma unroll
        for (int jb = 0; jb < 2; jb++)
#pragma unroll
            for (int i = 0; i < 4; i++)
#pragma unroll
                for (int j = 0; j < 4; j++) c[ia][jb][i][j] = 0.f;

    for (int k0 = 0; k0 < KK; k0 += 16) {
#pragma unroll
        for (int l = 0; l < 2; l++) {
            int idx = tid + l * 256;          // 0..511
            int row = idx >> 2;               // 0..127
            int qq  = idx & 3;                // which float4 within 16-wide k
            float4 av = *(const float4*)&A[(size_t)(bm + row) * KK + k0 + qq * 4];
            As[qq*4+0][row] = av.x; As[qq*4+1][row] = av.y;
            As[qq*4+2][row] = av.z; As[qq*4+3][row] = av.w;
            float4 wv = *(const float4*)&W[(size_t)(bn + row) * KK + k0 + qq * 4];
            Bs[qq*4+0][row] = wv.x; Bs[qq*4+1][row] = wv.y;
            Bs[qq*4+2][row] = wv.z; Bs[qq*4+3][row] = wv.w;
        }
        __syncthreads();

#pragma unroll
        for (int k = 0; k < 16; k++) {
            float a0[4], a1[4], b0[4], b1[4];
            *(float4*)a0 = *(const float4*)&As[k][ty * 4];
            *(float4*)a1 = *(const float4*)&As[k][64 + ty * 4];
            *(float4*)b0 = *(const float4*)&Bs[k][tx * 4];
            *(float4*)b1 = *(const float4*)&Bs[k][64 + tx * 4];
#pragma unroll
            for (int i = 0; i < 4; i++)
#pragma unroll
                for (int j = 0; j < 4; j++) {
                    c[0][0][i][j] += a0[i] * b0[j];
                    c[0][1][i][j] += a0[i] * b1[j];
                    c[1][0][i][j] += a1[i] * b0[j];
                    c[1][1][i][j] += a1[i] * b1[j];
                }
        }
        __syncthreads();
    }

#pragma unroll
    for (int ia = 0; ia < 2; ia++)
#pragma unroll
        for (int i = 0; i < 4; i++) {
            int mrow = bm + ia * 64 + ty * 4 + i;
            int b = mrow >> 11;        // / 2048
            int s = mrow & 2047;
#pragma unroll
            for (int jb = 0; jb < 2; jb++)
#pragma unroll
                for (int j = 0; j < 4; j++) {
                    int ncol = bn + jb * 64 + tx * 4 + j;
                    float val = c[ia][jb][i][j] + bias[ncol];
                    if (SPLIT) {
                        int h = ncol >> 6;
                        int d = ncol & 63;
                        C[(((size_t)(b * NHH + h)) * SS + s) * PHH + d] = val;
                    } else {
                        C[(size_t)mrow * HH + ncol] = val;
                    }
                }
        }
}

// ---------------------------------------------------------------------------
// Attention v2: GEMM-shaped flash attention.
// Grid (S/128, NH, B), 256 threads. 128 q-rows per CTA, k-tiles of 128.
// Score phase: 128x128 tile, 8x8 per thread (1 B/FMA).
// PV phase: 128x64 tile, 8 rows x 8 d-cols per thread over half the kk range
//           (parity split), partials combined in epilogue (1 B/FMA).
// Softmax: separate row pass over Ps with per-row m/l/corr state in smem.
// ---------------------------------------------------------------------------
#define PADQ 132   // stride for Qt/Kt [64][132]
#define PADV 68    // stride for Vs [128][68]
#define PADP 132   // stride for Ps [128][132]

#define ATTN2_SMEM ((64*PADQ*2 + 128*PADV + 128*PADP + 3*128) * 4)

__global__ __launch_bounds__(256) void attn2_kernel(const float* __restrict__ Q,
                                                    const float* __restrict__ K,
                                                    const float* __restrict__ V,
                                                    const float* __restrict__ mask,
                                                    float* __restrict__ ctx)
{
    extern __shared__ float sm[];
    float* Qt = sm;                       // [64][PADQ]  Qt[d][row]
    float* Kt = Qt + 64 * PADQ;           // [64][PADQ]  Kt[d][col]
    float* Vs = Kt + 64 * PADQ;           // [128][PADV] Vs[kk][d]
    float* Ps = Vs + 128 * PADV;          // [128][PADP] Ps[row][col]
    float* sm_m    = Ps + 128 * PADP;     // [128]
    float* sm_l    = sm_m + 128;          // [128]
    float* sm_corr = sm_l + 128;          // [128]

    const int t  = threadIdx.x;
    const int ti = t >> 4;                // 0..15  (8 q-rows each)
    const int tj = t & 15;                // 0..15
    const int r0 = ti * 8;
    const int cA = tj * 4;                // score cols: cA+j (j<4), 64+cA+(j-4)
    const int dj = tj & 7;
    const int p  = tj >> 3;               // kk parity
    const int dA = dj * 4;                // d cols: dA+j (j<4), 32+dA+(j-4)

    const int qt = blockIdx.x;
    const int h  = blockIdx.y;
    const int b  = blockIdx.z;
    const int q0 = qt * 128;

    const size_t headoff = ((size_t)(b * NHH + h)) * SS * PHH;
    const float* Qg = Q + headoff + (size_t)q0 * PHH;
    const float* Kg = K + headoff;
    const float* Vg = V + headoff;
    const float* Mg = mask + (size_t)b * SS * SS + (size_t)q0 * SS;

    // Load Q transposed: Qt[d][row]
    for (int i = t; i < 128 * 16; i += 256) {
        int row = i >> 4, qq = i & 15;
        float4 v = *(const float4*)&Qg[(size_t)row * 64 + qq * 4];
        Qt[(qq*4+0) * PADQ + row] = v.x;
        Qt[(qq*4+1) * PADQ + row] = v.y;
        Qt[(qq*4+2) * PADQ + row] = v.z;
        Qt[(qq*4+3) * PADQ + row] = v.w;
    }
    if (t < 128) { sm_m[t] = -3.0e38f; sm_l[t] = 0.f; }

    float o[64];
#pragma unroll
    for (int i = 0; i < 64; i++) o[i] = 0.f;

    for (int kt = 0; kt < SS / 128; kt++) {
        __syncthreads();   // previous PV done with Ps/Vs

        // Load K (transposed) and V tiles
        for (int i = t; i < 128 * 16; i += 256) {
            int row = i >> 4, qq = i & 15;
            const float* krow = &Kg[(size_t)(kt * 128 + row) * 64 + qq * 4];
            float4 kv = *(const float4*)krow;
            Kt[(qq*4+0) * PADQ + row] = kv.x;
            Kt[(qq*4+1) * PADQ + row] = kv.y;
            Kt[(qq*4+2) * PADQ + row] = kv.z;
            Kt[(qq*4+3) * PADQ + row] = kv.w;
            float4 vv = *(const float4*)&Vg[(size_t)(kt * 128 + row) * 64 + qq * 4];
            *(float4*)&Vs[row * PADV + qq * 4] = vv;
        }
        __syncthreads();

        // ---- score phase: acc[8][8] over d=0..63 ----
        float acc[8][8];
#pragma unroll
        for (int i = 0; i < 8; i++)
#pragma unroll
            for (int j = 0; j < 8; j++) acc[i][j] = 0.f;

#pragma unroll 8
        for (int d = 0; d < 64; d++) {
            float a[8], bv[8];
            *(float4*)&a[0]  = *(const float4*)&Qt[d * PADQ + r0];
            *(float4*)&a[4]  = *(const float4*)&Qt[d * PADQ + r0 + 4];
            *(float4*)&bv[0] = *(const float4*)&Kt[d * PADQ + cA];
            *(float4*)&bv[4] = *(const float4*)&Kt[d * PADQ + 64 + cA];
#pragma unroll
            for (int i = 0; i < 8; i++)
#pragma unroll
                for (int j = 0; j < 8; j++) acc[i][j] += a[i] * bv[j];
        }

        // scale + multiplicative mask, publish to Ps
#pragma unroll
        for (int i = 0; i < 8; i++) {
            int r = r0 + i;
            const float* mrow = &Mg[(size_t)r * SS + kt * 128];
            float4 m0 = *(const float4*)&mrow[cA];
            float4 m1 = *(const float4*)&mrow[64 + cA];
            float4 s0 = make_float4(acc[i][0] * 0.125f * m0.x,
                                    acc[i][1] * 0.125f * m0.y,
                                    acc[i][2] * 0.125f * m0.z,
                                    acc[i][3] * 0.125f * m0.w);
            float4 s1 = make_float4(acc[i][4] * 0.125f * m1.x,
                                    acc[i][5] * 0.125f * m1.y,
                                    acc[i][6] * 0.125f * m1.z,
                                    acc[i][7] * 0.125f * m1.w);
            *(float4*)&Ps[r * PADP + cA]      = s0;
            *(float4*)&Ps[r * PADP + 64 + cA] = s1;
        }
        __syncthreads();

        // ---- row softmax pass (2-pass over Ps, half-row per thread) ----
        {
            int row = t >> 1, hf = t & 1;
            float* prow = &Ps[row * PADP + hf * 64];
            float mx = -3.0e38f;
#pragma unroll
            for (int q = 0; q < 16; q++) {
                float4 v = ((const float4*)prow)[q];
                mx = fmaxf(mx, fmaxf(fmaxf(v.x, v.y), fmaxf(v.z, v.w)));
            }
            mx = fmaxf(mx, __shfl_xor_sync(0xffffffffu, mx, 1));
            float mold = sm_m[row];
            float mnew = fmaxf(mold, mx);
            float corr = __expf(mold - mnew);
            float ts = 0.f;
#pragma unroll
            for (int q = 0; q < 16; q++) {
                float4 v = ((const float4*)prow)[q];
                v.x = __expf(v.x - mnew);
                v.y = __expf(v.y - mnew);
                v.z = __expf(v.z - mnew);
                v.w = __expf(v.w - mnew);
                ((float4*)prow)[q] = v;
                ts += v.x + v.y + v.z + v.w;
            }
            ts += __shfl_xor_sync(0xffffffffu, ts, 1);
            if (hf == 0) {
                sm_m[row] = mnew;
                sm_l[row] = sm_l[row] * corr + ts;
                sm_corr[row] = corr;
            }
        }
        __syncthreads();

        // ---- PV phase: o[i][j] over half the kk range (parity split) ----
        float corr8[8];
#pragma unroll
        for (int i = 0; i < 8; i++) corr8[i] = sm_corr[r0 + i];
#pragma unroll
        for (int i = 0; i < 8; i++)
#pragma unroll
            for (int j = 0; j < 8; j++) o[i*8+j] *= corr8[i];

#pragma unroll 4
        for (int x = 0; x < 64; x++) {
            int kk = 2 * x + p;
            float pa[8], vb[8];
#pragma unroll
            for (int i = 0; i < 8; i++) pa[i] = Ps[(r0 + i) * PADP + kk];
            *(float4*)&vb[0] = *(const float4*)&Vs[kk * PADV + dA];
            *(float4*)&vb[4] = *(const float4*)&Vs[kk * PADV + 32 + dA];
#pragma unroll
            for (int i = 0; i < 8; i++)
#pragma unroll
                for (int j = 0; j < 8; j++) o[i*8+j] += pa[i] * vb[j];
        }
    }

    // ---- epilogue: combine parity halves via Ps, normalize, write ----
    __syncthreads();
    if (p == 1) {
#pragma unroll
        for (int i = 0; i < 8; i++) {
            int r = r0 + i;
#pragma unroll
            for (int j = 0; j < 8; j++) {
                int dcol = (j < 4) ? (dA + j) : (32 + dA + j - 4);
                Ps[r * PADP + dcol] = o[i*8+j];
            }
        }
    }
    __syncthreads();
    if (p == 0) {
#pragma unroll
        for (int i = 0; i < 8; i++) {
            int r = r0 + i;
            float inv = 1.f / sm_l[r];
            float* og = &ctx[((size_t)b * SS + q0 + r) * HH + h * PHH];
            float4 o0, o1;
            o0.x = (o[i*8+0] + Ps[r * PADP + dA + 0]) * inv;
            o0.y = (o[i*8+1] + Ps[r * PADP + dA + 1]) * inv;
            o0.z = (o[i*8+2] + Ps[r * PADP + dA + 2]) * inv;
            o0.w = (o[i*8+3] + Ps[r * PADP + dA + 3]) * inv;
            o1.x = (o[i*8+4] + Ps[r * PADP + 32 + dA + 0]) * inv;
            o1.y = (o[i*8+5] + Ps[r * PADP + 32 + dA + 1]) * inv;
            o1.z = (o[i*8+6] + Ps[r * PADP + 32 + dA + 2]) * inv;
            o1.w = (o[i*8+7] + Ps[r * PADP + 32 + dA + 3]) * inv;
            *(float4*)&og[dA]      = o0;
            *(float4*)&og[32 + dA] = o1;
        }
    }
}

// ---------------------------------------------------------------------------
// Launch
// ---------------------------------------------------------------------------
extern "C" void kernel_launch(void* const* d_in, const int* in_sizes, int n_in,
                              void* d_out, int out_size)
{
    const float* key   = (const float*)d_in[0];
    const float* value = (const float*)d_in[1];
    const float* query = (const float*)d_in[2];
    const float* mask  = (const float*)d_in[3];
    // d_in[4] = i (unused)
    const float* Wq = (const float*)d_in[5];
    const float* bq = (const float*)d_in[6];
    const float* Wk = (const float*)d_in[7];
    const float* bk = (const float*)d_in[8];
    const float* Wv = (const float*)d_in[9];
    const float* bv = (const float*)d_in[10];
    const float* Wo = (const float*)d_in[11];
    const float* bo = (const float*)d_in[12];
    float* out = (float*)d_out;

    float *qp, *kp, *vp, *cp;
    cudaGetSymbolAddress((void**)&qp, g_q);
    cudaGetSymbolAddress((void**)&kp, g_k);
    cudaGetSymbolAddress((void**)&vp, g_v);
    cudaGetSymbolAddress((void**)&cp, g_ctx);

    dim3 gg(HH / 128, MM / 128);   // (8, 32)

    gemm_nt<true><<<gg, 256>>>(query, Wq, bq, qp);
    gemm_nt<true><<<gg, 256>>>(key,   Wk, bk, kp);
    gemm_nt<true><<<gg, 256>>>(value, Wv, bv, vp);

    cudaFuncSetAttribute(attn2_kernel,
                         cudaFuncAttributeMaxDynamicSharedMemorySize, ATTN2_SMEM);
    attn2_kernel<<<dim3(SS / 128, NHH, BB), 256, ATTN2_SMEM>>>(qp, kp, vp, mask, cp);

    gemm_nt<false><<<gg, 256>>>(cp, Wo, bo, out);
}